// round 11
// baseline (speedup 1.0000x reference)
#include <cuda_runtime.h>
#include <cuda_bf16.h>
#include <stdint.h>

// GCNProtein: 6-layer GCN, 1M nodes, 16M edges, dims 1->3->3->3->3->3->1.
// FINAL — banked optimum, reproduced 4x (R4 760.4 / R7 760.0 / R10 760.5;
// R9's 1202us on identical bytes was environmental: L2 util 89%->65%).
//
// Design: flat edge-parallel scatter, 4 edges/thread via int4 index loads,
// exactly ONE red.global per edge (v4 for 3-wide layers, scalar for 1-wide),
// node transforms fused with norm scaling and agg zeroing. Algebraic
// minimization: norm commutes with W; W1 applied post-scatter (L1 scalar),
// W6 folded pre-scatter (L6 scalar) -> scatter widths 1,3,3,3,3,1.
//
// Locked cost model (R1/R4-R8): edge passes are bound purely by random L2
// op count at ~3.9us per million ops. 1 gather + 1 red per edge x 6 layers
// = 192M ops ~ 700us + ~55us streaming node kernels = ~755us floor.
// Falsified levers: per-thread widening/MLP/__ldcg (R5 neutral), index
// packing 128->80MB (R6 neutral), dst-sorted pull (R2: 15ms, serial
// divergent loops), dst-sorted push (R3: 16ms, line-hot atomic
// serialization), src-sorted push (R8: 944us, build cost exceeds the ~65us
// gather-collapse ceiling). Remaining headroom (L2 89->100%) is fixed by
// the graph's address-hash distribution over LTS slices, not kernel code.

#define NMAX 1000000

__device__ float4 g_x3[NMAX];    // 3-wide messages (padded to float4), layers 2-5
__device__ float4 g_agg3[NMAX];  // 3-wide accumulators (w stays 0)
__device__ float  g_x1[NMAX];    // scalar messages, layers 1 and 6
__device__ float  g_agg1[NMAX];  // scalar accumulator

__device__ __forceinline__ void red_add_f32(float* p, float v) {
    asm volatile("red.global.add.f32 [%0], %1;" :: "l"(p), "f"(v) : "memory");
}
__device__ __forceinline__ void red_add_v4_f32(float4* p, float4 v) {
    asm volatile("red.global.add.v4.f32 [%0], {%1, %2, %3, %4};"
                 :: "l"(p), "f"(v.x), "f"(v.y), "f"(v.z), "f"(v.w) : "memory");
}

// ---------------- node kernels ----------------

// layer 1 prologue: x1 = feat*norm ; agg1 = 0
__global__ void k_init(const float* __restrict__ feat, const float* __restrict__ norm, int n) {
    int i = blockIdx.x * blockDim.x + threadIdx.x;
    if (i < n) {
        g_x1[i] = feat[i] * norm[i];
        g_agg1[i] = 0.f;
    }
}

// after layer-1 scatter: h = relu((agg1*norm)*W1 + b1)  (W1 is 1x3)
// then prep layer 2: x3 = h*norm ; agg3 = 0
__global__ void k_node_1to3(const float* __restrict__ norm,
                            const float* __restrict__ W, const float* __restrict__ b, int n) {
    int i = blockIdx.x * blockDim.x + threadIdx.x;
    if (i >= n) return;
    float nm = norm[i];
    float t = g_agg1[i] * nm;
    float h0 = fmaxf(fmaf(t, W[0], b[0]), 0.f);
    float h1 = fmaxf(fmaf(t, W[1], b[1]), 0.f);
    float h2 = fmaxf(fmaf(t, W[2], b[2]), 0.f);
    g_x3[i] = make_float4(h0 * nm, h1 * nm, h2 * nm, 0.f);
    g_agg3[i] = make_float4(0.f, 0.f, 0.f, 0.f);
}

// after layer-l scatter (l in 2..4): h = relu((agg3*norm)@W + b)  (W is 3x3)
// then prep next layer: x3 = h*norm ; agg3 = 0
__global__ void k_node_3to3(const float* __restrict__ norm,
                            const float* __restrict__ W, const float* __restrict__ b, int n) {
    int i = blockIdx.x * blockDim.x + threadIdx.x;
    if (i >= n) return;
    float nm = norm[i];
    float4 a = g_agg3[i];
    float a0 = a.x * nm, a1 = a.y * nm, a2 = a.z * nm;
    float h0 = fmaxf(fmaf(a0, W[0], fmaf(a1, W[3], fmaf(a2, W[6], b[0]))), 0.f);
    float h1 = fmaxf(fmaf(a0, W[1], fmaf(a1, W[4], fmaf(a2, W[7], b[1]))), 0.f);
    float h2 = fmaxf(fmaf(a0, W[2], fmaf(a1, W[5], fmaf(a2, W[8], b[2]))), 0.f);
    g_x3[i] = make_float4(h0 * nm, h1 * nm, h2 * nm, 0.f);
    g_agg3[i] = make_float4(0.f, 0.f, 0.f, 0.f);
}

// after layer-5 scatter: h5 = relu((agg3*norm)@W5 + b5), fold W6 (3x1):
// x1 = norm*(h5@W6) ; agg1 = 0
__global__ void k_node_3to_scalar(const float* __restrict__ norm,
                                  const float* __restrict__ W5, const float* __restrict__ b5,
                                  const float* __restrict__ W6, int n) {
    int i = blockIdx.x * blockDim.x + threadIdx.x;
    if (i >= n) return;
    float nm = norm[i];
    float4 a = g_agg3[i];
    float a0 = a.x * nm, a1 = a.y * nm, a2 = a.z * nm;
    float h0 = fmaxf(fmaf(a0, W5[0], fmaf(a1, W5[3], fmaf(a2, W5[6], b5[0]))), 0.f);
    float h1 = fmaxf(fmaf(a0, W5[1], fmaf(a1, W5[4], fmaf(a2, W5[7], b5[1]))), 0.f);
    float h2 = fmaxf(fmaf(a0, W5[2], fmaf(a1, W5[5], fmaf(a2, W5[8], b5[2]))), 0.f);
    g_x1[i] = nm * (h0 * W6[0] + h1 * W6[1] + h2 * W6[2]);
    g_agg1[i] = 0.f;
}

// after layer-6 scatter: out = relu(norm*agg1 + b6)
__global__ void k_node_final(const float* __restrict__ norm,
                             const float* __restrict__ b6,
                             float* __restrict__ out, int n) {
    int i = blockIdx.x * blockDim.x + threadIdx.x;
    if (i >= n) return;
    out[i] = fmaxf(fmaf(norm[i], g_agg1[i], b6[0]), 0.f);
}

// ---------------- edge kernels (4 edges/thread, int4 index loads) ----------------

// scalar scatter: agg1[dst] += x1[src], 4 edges per thread
__global__ void k_edge_s4(const int4* __restrict__ src4, const int4* __restrict__ dst4, int nq) {
    int t = blockIdx.x * blockDim.x + threadIdx.x;
    if (t >= nq) return;
    int4 s = src4[t];
    int4 d = dst4[t];
    float v0 = g_x1[s.x];
    float v1 = g_x1[s.y];
    float v2 = g_x1[s.z];
    float v3 = g_x1[s.w];
    red_add_f32(&g_agg1[d.x], v0);
    red_add_f32(&g_agg1[d.y], v1);
    red_add_f32(&g_agg1[d.z], v2);
    red_add_f32(&g_agg1[d.w], v3);
}

// 3-wide scatter: agg3[dst] += x3[src] via one v4 red per edge (w lane adds 0)
__global__ void k_edge_v4(const int4* __restrict__ src4, const int4* __restrict__ dst4, int nq) {
    int t = blockIdx.x * blockDim.x + threadIdx.x;
    if (t >= nq) return;
    int4 s = src4[t];
    int4 d = dst4[t];
    float4 v0 = g_x3[s.x];
    float4 v1 = g_x3[s.y];
    float4 v2 = g_x3[s.z];
    float4 v3 = g_x3[s.w];
    red_add_v4_f32(&g_agg3[d.x], v0);
    red_add_v4_f32(&g_agg3[d.y], v1);
    red_add_v4_f32(&g_agg3[d.z], v2);
    red_add_v4_f32(&g_agg3[d.w], v3);
}

// ---------------- launch ----------------

extern "C" void kernel_launch(void* const* d_in, const int* in_sizes, int n_in,
                              void* d_out, int out_size) {
    // Identify inputs by element count:
    //   ~16M ints  -> src, dst (in order)
    //   ~1M floats -> feat, norm (in order)
    //   small      -> W1,b1,...,W6,b6 (in order)
    const int* big_i[2] = {nullptr, nullptr};
    const float* big_f[2] = {nullptr, nullptr};
    const float* small[12] = {nullptr};
    int ni = 0, nf = 0, ns = 0;
    int N = 0, E = 0;
    for (int i = 0; i < n_in; i++) {
        int sz = in_sizes[i];
        if (sz >= 10000000) {
            if (ni < 2) { big_i[ni++] = (const int*)d_in[i]; E = sz; }
        } else if (sz >= 100000) {
            if (nf < 2) { big_f[nf++] = (const float*)d_in[i]; N = sz; }
        } else {
            if (ns < 12) small[ns++] = (const float*)d_in[i];
        }
    }
    const float* feat = big_f[0];
    const float* norm = big_f[1];
    const int4* src4 = (const int4*)big_i[0];
    const int4* dst4 = (const int4*)big_i[1];
    const float *W1 = small[0], *b1 = small[1];
    const float *W2 = small[2], *b2 = small[3];
    const float *W3 = small[4], *b3 = small[5];
    const float *W4 = small[6], *b4 = small[7];
    const float *W5 = small[8], *b5 = small[9];
    const float *W6 = small[10], *b6 = small[11];
    float* out = (float*)d_out;

    const int TB = 256;
    int gn = (N + TB - 1) / TB;
    int nq = E / 4;                      // E = 16M, divisible by 4
    int gq = (nq + TB - 1) / TB;

    // L1 (scalar messages)
    k_init<<<gn, TB>>>(feat, norm, N);
    k_edge_s4<<<gq, TB>>>(src4, dst4, nq);
    k_node_1to3<<<gn, TB>>>(norm, W1, b1, N);
    // L2..L4 (3-wide)
    k_edge_v4<<<gq, TB>>>(src4, dst4, nq);
    k_node_3to3<<<gn, TB>>>(norm, W2, b2, N);
    k_edge_v4<<<gq, TB>>>(src4, dst4, nq);
    k_node_3to3<<<gn, TB>>>(norm, W3, b3, N);
    k_edge_v4<<<gq, TB>>>(src4, dst4, nq);
    k_node_3to3<<<gn, TB>>>(norm, W4, b4, N);
    // L5 (3-wide scatter, then fold W6 so L6 messages are scalar)
    k_edge_v4<<<gq, TB>>>(src4, dst4, nq);
    k_node_3to_scalar<<<gn, TB>>>(norm, W5, b5, W6, N);
    // L6 (scalar)
    k_edge_s4<<<gq, TB>>>(src4, dst4, nq);
    k_node_final<<<gn, TB>>>(norm, b6, out, N);
}

// round 12
// speedup vs baseline: 1.0034x; 1.0034x over previous
#include <cuda_runtime.h>
#include <cuda_bf16.h>
#include <stdint.h>

// GCNProtein: 6-layer GCN, 1M nodes, 16M edges, dims 1->3->3->3->3->3->1.
// FINAL — banked optimum, reproduced 5x (R4 760.4 / R7 760.0 / R10 760.5 /
// R11 760.9; R9's 1202us on identical bytes was environmental: L2 util
// dropped 89%->65% at identical SASS/occupancy).
//
// Design: flat edge-parallel scatter, 4 edges/thread via int4 index loads,
// exactly ONE red.global per edge (v4 for 3-wide layers, scalar for 1-wide),
// node transforms fused with norm scaling and agg zeroing. Algebraic
// minimization: norm commutes with W; W1 applied post-scatter (L1 scalar),
// W6 folded pre-scatter (L6 scalar) -> scatter widths 1,3,3,3,3,1.
//
// Locked cost model (R1/R4-R8): edge passes are bound purely by random L2
// op count at ~3.9us per million ops. 1 gather + 1 red per edge x 6 layers
// = 192M ops ~ 700us + ~55us streaming node kernels = ~755us floor; kernel
// sits on it at 89% LTS utilization (residual fixed by the graph's
// address-hash spread over LTS slices, not kernel code).
// Falsified levers: per-thread widening/MLP/__ldcg (R5 neutral), index
// packing 128->80MB (R6 neutral), dst-sorted pull (R2: 15ms, serial
// divergent loops), dst-sorted push (R3: 16ms, line-hot atomic
// serialization), src-sorted push (R8: 944us, build cost exceeds the ~65us
// gather-collapse ceiling). Cross-layer fusion blocked by ReLU; duplicate /
// warp-shared dst rates are ~0.003%/0.05% (worthless).

#define NMAX 1000000

__device__ float4 g_x3[NMAX];    // 3-wide messages (padded to float4), layers 2-5
__device__ float4 g_agg3[NMAX];  // 3-wide accumulators (w stays 0)
__device__ float  g_x1[NMAX];    // scalar messages, layers 1 and 6
__device__ float  g_agg1[NMAX];  // scalar accumulator

__device__ __forceinline__ void red_add_f32(float* p, float v) {
    asm volatile("red.global.add.f32 [%0], %1;" :: "l"(p), "f"(v) : "memory");
}
__device__ __forceinline__ void red_add_v4_f32(float4* p, float4 v) {
    asm volatile("red.global.add.v4.f32 [%0], {%1, %2, %3, %4};"
                 :: "l"(p), "f"(v.x), "f"(v.y), "f"(v.z), "f"(v.w) : "memory");
}

// ---------------- node kernels ----------------

// layer 1 prologue: x1 = feat*norm ; agg1 = 0
__global__ void k_init(const float* __restrict__ feat, const float* __restrict__ norm, int n) {
    int i = blockIdx.x * blockDim.x + threadIdx.x;
    if (i < n) {
        g_x1[i] = feat[i] * norm[i];
        g_agg1[i] = 0.f;
    }
}

// after layer-1 scatter: h = relu((agg1*norm)*W1 + b1)  (W1 is 1x3)
// then prep layer 2: x3 = h*norm ; agg3 = 0
__global__ void k_node_1to3(const float* __restrict__ norm,
                            const float* __restrict__ W, const float* __restrict__ b, int n) {
    int i = blockIdx.x * blockDim.x + threadIdx.x;
    if (i >= n) return;
    float nm = norm[i];
    float t = g_agg1[i] * nm;
    float h0 = fmaxf(fmaf(t, W[0], b[0]), 0.f);
    float h1 = fmaxf(fmaf(t, W[1], b[1]), 0.f);
    float h2 = fmaxf(fmaf(t, W[2], b[2]), 0.f);
    g_x3[i] = make_float4(h0 * nm, h1 * nm, h2 * nm, 0.f);
    g_agg3[i] = make_float4(0.f, 0.f, 0.f, 0.f);
}

// after layer-l scatter (l in 2..4): h = relu((agg3*norm)@W + b)  (W is 3x3)
// then prep next layer: x3 = h*norm ; agg3 = 0
__global__ void k_node_3to3(const float* __restrict__ norm,
                            const float* __restrict__ W, const float* __restrict__ b, int n) {
    int i = blockIdx.x * blockDim.x + threadIdx.x;
    if (i >= n) return;
    float nm = norm[i];
    float4 a = g_agg3[i];
    float a0 = a.x * nm, a1 = a.y * nm, a2 = a.z * nm;
    float h0 = fmaxf(fmaf(a0, W[0], fmaf(a1, W[3], fmaf(a2, W[6], b[0]))), 0.f);
    float h1 = fmaxf(fmaf(a0, W[1], fmaf(a1, W[4], fmaf(a2, W[7], b[1]))), 0.f);
    float h2 = fmaxf(fmaf(a0, W[2], fmaf(a1, W[5], fmaf(a2, W[8], b[2]))), 0.f);
    g_x3[i] = make_float4(h0 * nm, h1 * nm, h2 * nm, 0.f);
    g_agg3[i] = make_float4(0.f, 0.f, 0.f, 0.f);
}

// after layer-5 scatter: h5 = relu((agg3*norm)@W5 + b5), fold W6 (3x1):
// x1 = norm*(h5@W6) ; agg1 = 0
__global__ void k_node_3to_scalar(const float* __restrict__ norm,
                                  const float* __restrict__ W5, const float* __restrict__ b5,
                                  const float* __restrict__ W6, int n) {
    int i = blockIdx.x * blockDim.x + threadIdx.x;
    if (i >= n) return;
    float nm = norm[i];
    float4 a = g_agg3[i];
    float a0 = a.x * nm, a1 = a.y * nm, a2 = a.z * nm;
    float h0 = fmaxf(fmaf(a0, W5[0], fmaf(a1, W5[3], fmaf(a2, W5[6], b5[0]))), 0.f);
    float h1 = fmaxf(fmaf(a0, W5[1], fmaf(a1, W5[4], fmaf(a2, W5[7], b5[1]))), 0.f);
    float h2 = fmaxf(fmaf(a0, W5[2], fmaf(a1, W5[5], fmaf(a2, W5[8], b5[2]))), 0.f);
    g_x1[i] = nm * (h0 * W6[0] + h1 * W6[1] + h2 * W6[2]);
    g_agg1[i] = 0.f;
}

// after layer-6 scatter: out = relu(norm*agg1 + b6)
__global__ void k_node_final(const float* __restrict__ norm,
                             const float* __restrict__ b6,
                             float* __restrict__ out, int n) {
    int i = blockIdx.x * blockDim.x + threadIdx.x;
    if (i >= n) return;
    out[i] = fmaxf(fmaf(norm[i], g_agg1[i], b6[0]), 0.f);
}

// ---------------- edge kernels (4 edges/thread, int4 index loads) ----------------

// scalar scatter: agg1[dst] += x1[src], 4 edges per thread
__global__ void k_edge_s4(const int4* __restrict__ src4, const int4* __restrict__ dst4, int nq) {
    int t = blockIdx.x * blockDim.x + threadIdx.x;
    if (t >= nq) return;
    int4 s = src4[t];
    int4 d = dst4[t];
    float v0 = g_x1[s.x];
    float v1 = g_x1[s.y];
    float v2 = g_x1[s.z];
    float v3 = g_x1[s.w];
    red_add_f32(&g_agg1[d.x], v0);
    red_add_f32(&g_agg1[d.y], v1);
    red_add_f32(&g_agg1[d.z], v2);
    red_add_f32(&g_agg1[d.w], v3);
}

// 3-wide scatter: agg3[dst] += x3[src] via one v4 red per edge (w lane adds 0)
__global__ void k_edge_v4(const int4* __restrict__ src4, const int4* __restrict__ dst4, int nq) {
    int t = blockIdx.x * blockDim.x + threadIdx.x;
    if (t >= nq) return;
    int4 s = src4[t];
    int4 d = dst4[t];
    float4 v0 = g_x3[s.x];
    float4 v1 = g_x3[s.y];
    float4 v2 = g_x3[s.z];
    float4 v3 = g_x3[s.w];
    red_add_v4_f32(&g_agg3[d.x], v0);
    red_add_v4_f32(&g_agg3[d.y], v1);
    red_add_v4_f32(&g_agg3[d.z], v2);
    red_add_v4_f32(&g_agg3[d.w], v3);
}

// ---------------- launch ----------------

extern "C" void kernel_launch(void* const* d_in, const int* in_sizes, int n_in,
                              void* d_out, int out_size) {
    // Identify inputs by element count:
    //   ~16M ints  -> src, dst (in order)
    //   ~1M floats -> feat, norm (in order)
    //   small      -> W1,b1,...,W6,b6 (in order)
    const int* big_i[2] = {nullptr, nullptr};
    const float* big_f[2] = {nullptr, nullptr};
    const float* small[12] = {nullptr};
    int ni = 0, nf = 0, ns = 0;
    int N = 0, E = 0;
    for (int i = 0; i < n_in; i++) {
        int sz = in_sizes[i];
        if (sz >= 10000000) {
            if (ni < 2) { big_i[ni++] = (const int*)d_in[i]; E = sz; }
        } else if (sz >= 100000) {
            if (nf < 2) { big_f[nf++] = (const float*)d_in[i]; N = sz; }
        } else {
            if (ns < 12) small[ns++] = (const float*)d_in[i];
        }
    }
    const float* feat = big_f[0];
    const float* norm = big_f[1];
    const int4* src4 = (const int4*)big_i[0];
    const int4* dst4 = (const int4*)big_i[1];
    const float *W1 = small[0], *b1 = small[1];
    const float *W2 = small[2], *b2 = small[3];
    const float *W3 = small[4], *b3 = small[5];
    const float *W4 = small[6], *b4 = small[7];
    const float *W5 = small[8], *b5 = small[9];
    const float *W6 = small[10], *b6 = small[11];
    float* out = (float*)d_out;

    const int TB = 256;
    int gn = (N + TB - 1) / TB;
    int nq = E / 4;                      // E = 16M, divisible by 4
    int gq = (nq + TB - 1) / TB;

    // L1 (scalar messages)
    k_init<<<gn, TB>>>(feat, norm, N);
    k_edge_s4<<<gq, TB>>>(src4, dst4, nq);
    k_node_1to3<<<gn, TB>>>(norm, W1, b1, N);
    // L2..L4 (3-wide)
    k_edge_v4<<<gq, TB>>>(src4, dst4, nq);
    k_node_3to3<<<gn, TB>>>(norm, W2, b2, N);
    k_edge_v4<<<gq, TB>>>(src4, dst4, nq);
    k_node_3to3<<<gn, TB>>>(norm, W3, b3, N);
    k_edge_v4<<<gq, TB>>>(src4, dst4, nq);
    k_node_3to3<<<gn, TB>>>(norm, W4, b4, N);
    // L5 (3-wide scatter, then fold W6 so L6 messages are scalar)
    k_edge_v4<<<gq, TB>>>(src4, dst4, nq);
    k_node_3to_scalar<<<gn, TB>>>(norm, W5, b5, W6, N);
    // L6 (scalar)
    k_edge_s4<<<gq, TB>>>(src4, dst4, nq);
    k_node_final<<<gn, TB>>>(norm, b6, out, N);
}